// round 16
// baseline (speedup 1.0000x reference)
#include <cuda_runtime.h>
#include <math_constants.h>
#include <cuda_fp16.h>
#include <cstdint>

// Problem constants
#define BB 1024   // batch
#define CC 32     // classes
#define KK 16     // prototypes per class
#define DD 256    // embedding dim
#define TWO_D 512

// Scratch (static device arrays — no allocation allowed)
__device__ float g_proto_term[CC * KK * DD];          // 512 KB
__device__ float g_dotep[(size_t)BB * CC * KK];       // 2 MB: emb·proto
__device__ float g_G[CC * KK * KK];                   // 32 KB: Gram
__device__ float g_e2[BB];                            // |emb|^2
__device__ float g_inval[CC * KK];                    // 0 = valid, -inf = invalid
__device__ __half g_emb_h[(size_t)BB * DD];           // 512 KB: emb as half
__device__ __half g_W1h[(size_t)CC * DD * DD];        // 4 MB: W1top^T as half [c][n][k]

__device__ __forceinline__ uint32_t f2tf(float f) {
    uint32_t r;
    asm("cvt.rna.tf32.f32 %0, %1;" : "=r"(r) : "f"(f));
    return r;
}
__device__ __forceinline__ __half2 tanh_h2(__half2 x) {
    uint32_t xi = *reinterpret_cast<uint32_t*>(&x);
    uint32_t r;
    asm("tanh.approx.f16x2 %0, %1;" : "=r"(r) : "r"(xi));
    return *reinterpret_cast<__half2*>(&r);
}
__device__ __forceinline__ uint32_t h2u(__half2 h) {
    return *reinterpret_cast<uint32_t*>(&h);
}
__device__ __forceinline__ void cp16(void* smem, const void* g) {
    uint32_t sa = (uint32_t)__cvta_generic_to_shared(smem);
    asm volatile("cp.async.cg.shared.global [%0], [%1], 16;" :: "r"(sa), "l"(g));
}
#define CP_COMMIT() asm volatile("cp.async.commit_group;")
#define CP_WAIT(N)  asm volatile("cp.async.wait_group %0;" :: "n"(N))

__device__ __forceinline__ void mma_tf32(float c_[4], const uint32_t a[4], const uint32_t b[2]) {
    asm volatile(
        "mma.sync.aligned.m16n8k8.row.col.f32.tf32.tf32.f32 "
        "{%0,%1,%2,%3}, {%4,%5,%6,%7}, {%8,%9}, {%0,%1,%2,%3};"
        : "+f"(c_[0]), "+f"(c_[1]), "+f"(c_[2]), "+f"(c_[3])
        : "r"(a[0]), "r"(a[1]), "r"(a[2]), "r"(a[3]), "r"(b[0]), "r"(b[1]));
}
// fp16 inputs, fp32 accumulate (used by 2nd-stage score mma)
__device__ __forceinline__ void mma_f16(float c_[4],
    uint32_t a0, uint32_t a1, uint32_t a2, uint32_t a3,
    uint32_t b0, uint32_t b1) {
    asm volatile(
        "mma.sync.aligned.m16n8k16.row.col.f32.f16.f16.f32 "
        "{%0,%1,%2,%3}, {%4,%5,%6,%7}, {%8,%9}, {%0,%1,%2,%3};"
        : "+f"(c_[0]), "+f"(c_[1]), "+f"(c_[2]), "+f"(c_[3])
        : "r"(a0), "r"(a1), "r"(a2), "r"(a3), "r"(b0), "r"(b1));
}
// fp16 inputs, fp16 accumulate (GEMM phase — C/D = 2 regs)
__device__ __forceinline__ void mma_f16_hacc(uint32_t c_[2],
    uint32_t a0, uint32_t a1, uint32_t a2, uint32_t a3,
    uint32_t b0, uint32_t b1) {
    asm volatile(
        "mma.sync.aligned.m16n8k16.row.col.f16.f16.f16.f16 "
        "{%0,%1}, {%2,%3,%4,%5}, {%6,%7}, {%0,%1};"
        : "+r"(c_[0]), "+r"(c_[1])
        : "r"(a0), "r"(a1), "r"(a2), "r"(a3), "r"(b0), "r"(b1));
}

// ===========================================================================
// Kernel A (prologue, fused): blockIdx dispatch, 256 threads, dynamic smem
//   [0,32)    : proto_term tf32 mma, BK=16, 3-stage, 1 sync/iter
//   [32,64)   : Gram        (c = blk-32)
//   [64,96)   : e2 + emb->half
//   96        : decode prototype_valid mask
//   [97,161)  : dotep tf32 GEMM, BK=16, 3-stage, 1 sync/iter
//   [161,417) : W1top transpose->half (c = idx>>3, tj = (idx>>1)&3, th = idx&1)
// ===========================================================================
__global__ __launch_bounds__(256) void prologue_kernel(
    const float* __restrict__ emb,      // [B,D]
    const float* __restrict__ protos,   // [C,K,D]
    const float* __restrict__ W1,       // [C,2D,D]
    const float* __restrict__ b1,       // [C,D]
    const void*  __restrict__ valid)
{
    extern __shared__ __align__(16) float sh[];
    const int blk = blockIdx.x;
    const int tid = threadIdx.x;

    if (blk < 32) {
        // ----- proto_term[c] = protos[c] @ W1bot[c] + b1[c]  (tf32 mma)
        // M=16, N=256, K=256, BK=16, 3-stage cp.async, one sync per iter.
        const int c = blk;
        float* As = sh;             // [16][260] = 4160 words
        float* Bs = sh + 4160;      // [3][16][264] = 12672 words

        const int warp = tid >> 5, lane = tid & 31;
        const int wn = warp * 32;
        const int g  = lane >> 2, tg = lane & 3;

        const float* pg = protos + (size_t)c * KK * DD;
        #pragma unroll
        for (int i = 0; i < 16; ++i) {
            int idx = tid + i * 256;
            As[(idx >> 8) * 260 + (idx & 255)] = pg[idx];
        }
        // As stores ordered by first in-loop __syncthreads (iteration 0).

        const float* Wb = W1 + ((size_t)c * TWO_D + DD) * DD;   // [256 k][256 n]
        #define PT_LOAD(s, kbase)                                               \
            {                                                                    \
                _Pragma("unroll")                                                \
                for (int i_ = 0; i_ < 4; ++i_) {                                 \
                    int slot = tid + i_ * 256;                                   \
                    int k = slot >> 6, n4 = (slot & 63) << 2;                    \
                    cp16(&Bs[(s) * 4224 + k * 264 + n4],                         \
                         Wb + (size_t)((kbase) + k) * DD + n4);                  \
                }                                                                \
                CP_COMMIT();                                                     \
            }

        PT_LOAD(0, 0);
        PT_LOAD(1, 16);
        float accp[4][4];
        #pragma unroll
        for (int j = 0; j < 4; ++j)
            #pragma unroll
            for (int t = 0; t < 4; ++t) accp[j][t] = 0.f;

        const int NT = 16;
        #pragma unroll 1
        for (int kt = 0; kt < NT; ++kt) {
            const int cs = kt % 3;
            if (kt < NT - 1) { CP_WAIT(1); } else { CP_WAIT(0); }
            __syncthreads();
            if (kt + 2 < NT) PT_LOAD((kt + 2) % 3, (kt + 2) * 16);

            #pragma unroll
            for (int ks = 0; ks < 2; ++ks) {
                const int kb = kt * 16 + ks * 8;
                uint32_t afr[4], bfr[4][2];
                afr[0] = f2tf(As[g * 260 + kb + tg]);
                afr[1] = f2tf(As[(g + 8) * 260 + kb + tg]);
                afr[2] = f2tf(As[g * 260 + kb + tg + 4]);
                afr[3] = f2tf(As[(g + 8) * 260 + kb + tg + 4]);
                #pragma unroll
                for (int j = 0; j < 4; ++j) {
                    int n0 = wn + j * 8;
                    bfr[j][0] = f2tf(Bs[cs * 4224 + (ks * 8 + tg) * 264 + n0 + g]);
                    bfr[j][1] = f2tf(Bs[cs * 4224 + (ks * 8 + tg + 4) * 264 + n0 + g]);
                }
                #pragma unroll
                for (int j = 0; j < 4; ++j)
                    mma_tf32(accp[j], afr, bfr[j]);
            }
        }

        #pragma unroll
        for (int j = 0; j < 4; ++j) {
            int col = wn + j * 8 + 2 * tg;
            float2 b1v = *(const float2*)&b1[c * DD + col];
            *(float2*)&g_proto_term[((c * KK) + g) * DD + col] =
                make_float2(accp[j][0] + b1v.x, accp[j][1] + b1v.y);
            *(float2*)&g_proto_term[((c * KK) + g + 8) * DD + col] =
                make_float2(accp[j][2] + b1v.x, accp[j][3] + b1v.y);
        }
        #undef PT_LOAD

    } else if (blk < 64) {
        // ----- Gram G[c][k][k2]
        const int c = blk - 32;
        float* p_s = sh;   // [16][257]
        for (int i = tid; i < KK * DD; i += 256) {
            int k = i / DD, d = i % DD;
            p_s[k * (DD + 1) + d] = protos[(size_t)c * KK * DD + i];
        }
        __syncthreads();
        const int k = tid >> 4, k2 = tid & 15;
        float s = 0.f;
        #pragma unroll 4
        for (int d = 0; d < DD; ++d)
            s = fmaf(p_s[k * (DD + 1) + d], p_s[k2 * (DD + 1) + d], s);
        g_G[c * 256 + tid] = s;

    } else if (blk < 96) {
        // ----- e2 + emb->half: warp-per-row, 4 rows per warp
        const int warp = tid >> 5, lane = tid & 31;
        const int base = (blk - 64) * 32 + warp * 4;
        #pragma unroll
        for (int t = 0; t < 4; ++t) {
            const int b = base + t;
            const float4* p = (const float4*)(emb + (size_t)b * DD);
            float4 v0 = p[lane], v1 = p[lane + 32];
            uint2* eh = (uint2*)(g_emb_h + (size_t)b * DD);
            uint2 w0, w1;
            w0.x = h2u(__floats2half2_rn(v0.x, v0.y));
            w0.y = h2u(__floats2half2_rn(v0.z, v0.w));
            w1.x = h2u(__floats2half2_rn(v1.x, v1.y));
            w1.y = h2u(__floats2half2_rn(v1.z, v1.w));
            eh[lane]      = w0;
            eh[lane + 32] = w1;
            float s = v0.x*v0.x + v0.y*v0.y + v0.z*v0.z + v0.w*v0.w
                    + v1.x*v1.x + v1.y*v1.y + v1.z*v1.z + v1.w*v1.w;
            #pragma unroll
            for (int off = 16; off > 0; off >>= 1)
                s += __shfl_xor_sync(0xFFFFFFFFu, s, off);
            if (lane == 0) g_e2[b] = s;
        }

    } else if (blk == 96) {
        // ----- decode prototype_valid (dtype-sniffing)
        __shared__ int s_hasF, s_hasHi, s_mode;
        if (tid == 0) { s_hasF = 0; s_hasHi = 0; }
        __syncthreads();
        if (tid < 128) {
            unsigned v = ((const unsigned*)valid)[tid];
            if (v == 0x3F800000u)                        atomicOr(&s_hasF, 1);
            else if (v != 0u && (v & 0xFFFFFF00u) != 0u) atomicOr(&s_hasHi, 1);
        }
        __syncthreads();
        if (tid == 0) s_mode = s_hasF ? 0 : (s_hasHi ? 2 : 1);
        __syncthreads();
        const int mode = s_mode;
        for (int i = tid; i < CC * KK; i += 256) {
            bool v;
            if (mode == 0)      v = ((const float*)valid)[i] != 0.0f;
            else if (mode == 1) v = ((const int*)valid)[i] != 0;
            else                v = ((const unsigned char*)valid)[i] != 0;
            g_inval[i] = v ? 0.0f : -CUDART_INF_F;
        }

    } else if (blk < 161) {
        // ----- dotep[b][ck] = emb·proto  (tf32 mma), 3-stage, 1 sync/iter
        const int b    = blk - 97;               // 0..63
        const int bm0  = (b >> 2) * 64;
        const int bn0  = (b & 3) * 128;

        #define DAS(s, m, k) sh[(s) * 1280 + (m) * 20 + (k)]
        #define DPS(s, n, k) sh[3840 + (s) * 2560 + (n) * 20 + (k)]

        const int warp = tid >> 5, lane = tid & 31;
        const int wm = (warp >> 2) * 32;
        const int wn = (warp & 3) * 32;
        const int g  = lane >> 2, tg = lane & 3;

        float acc[2][4][4];
        #pragma unroll
        for (int i = 0; i < 2; ++i)
            #pragma unroll
            for (int j = 0; j < 4; ++j)
                #pragma unroll
                for (int t = 0; t < 4; ++t) acc[i][j][t] = 0.f;

        #define DE_LOAD(s, kbase)                                                         \
            {                                                                              \
                { int m = tid >> 2, k4 = (tid & 3) << 2;                                   \
                  cp16(&DAS(s, m, k4), emb + (size_t)(bm0 + m) * DD + (kbase) + k4); }     \
                _Pragma("unroll")                                                          \
                for (int i_ = 0; i_ < 2; ++i_) {                                           \
                    int slot = tid + i_ * 256;                                             \
                    int n = slot >> 2, k4 = (slot & 3) << 2;                               \
                    cp16(&DPS(s, n, k4), protos + (size_t)(bn0 + n) * DD + (kbase) + k4);  \
                }                                                                          \
                CP_COMMIT();                                                               \
            }

        DE_LOAD(0, 0);
        DE_LOAD(1, 16);
        const int NT = DD / 16;   // 16
        #pragma unroll 1
        for (int kt = 0; kt < NT; ++kt) {
            const int cs = kt % 3;
            if (kt < NT - 1) { CP_WAIT(1); } else { CP_WAIT(0); }
            __syncthreads();
            if (kt + 2 < NT) DE_LOAD((kt + 2) % 3, (kt + 2) * 16);

            #pragma unroll
            for (int ks = 0; ks < 2; ++ks) {
                const int kb = ks * 8;
                uint32_t afr[2][4], bfr[4][2];
                #pragma unroll
                for (int i = 0; i < 2; ++i) {
                    int m0 = wm + i * 16;
                    afr[i][0] = f2tf(DAS(cs, m0 + g,     kb + tg));
                    afr[i][1] = f2tf(DAS(cs, m0 + g + 8, kb + tg));
                    afr[i][2] = f2tf(DAS(cs, m0 + g,     kb + tg + 4));
                    afr[i][3] = f2tf(DAS(cs, m0 + g + 8, kb + tg + 4));
                }
                #pragma unroll
                for (int j = 0; j < 4; ++j) {
                    int n0 = wn + j * 8;
                    bfr[j][0] = f2tf(DPS(cs, n0 + g, kb + tg));
                    bfr[j][1] = f2tf(DPS(cs, n0 + g, kb + tg + 4));
                }
                #pragma unroll
                for (int i = 0; i < 2; ++i)
                    #pragma unroll
                    for (int j = 0; j < 4; ++j)
                        mma_tf32(acc[i][j], afr[i], bfr[j]);
            }
        }

        #pragma unroll
        for (int i = 0; i < 2; ++i) {
            int r0 = bm0 + wm + i * 16 + g;
            #pragma unroll
            for (int j = 0; j < 4; ++j) {
                int col = bn0 + wn + j * 8 + 2 * tg;
                *(float2*)(g_dotep + (size_t)r0 * (CC * KK) + col)       = make_float2(acc[i][j][0], acc[i][j][1]);
                *(float2*)(g_dotep + (size_t)(r0 + 8) * (CC * KK) + col) = make_float2(acc[i][j][2], acc[i][j][3]);
            }
        }
        #undef DE_LOAD
        #undef DAS
        #undef DPS

    } else {
        // ----- W1top -> g_W1h[c][n][k] (transpose + half convert), 8 blocks/class
        const int idx = blk - 161;           // 0..255
        const int c  = idx >> 3;
        const int tj = (idx >> 1) & 3;       // 64-wide n slice
        const int th = idx & 1;              // handles ti = 2*th, 2*th+1
        float* ts = sh;                      // [64][65]
        const float* Wt = W1 + (size_t)c * TWO_D * DD;   // top half [256 k][256 n]
        __half* outc = g_W1h + (size_t)c * DD * DD;

        for (int tq = 0; tq < 2; ++tq) {
            const int ti = 2 * th + tq;
            {
                int r = tid >> 2, cg = (tid & 3) * 16;
                const float* src = Wt + (size_t)(ti * 64 + r) * DD + tj * 64 + cg;
                #pragma unroll
                for (int u = 0; u < 4; ++u) {
                    float4 v = *(const float4*)(src + u * 4);
                    ts[r * 65 + cg + u * 4 + 0] = v.x;
                    ts[r * 65 + cg + u * 4 + 1] = v.y;
                    ts[r * 65 + cg + u * 4 + 2] = v.z;
                    ts[r * 65 + cg + u * 4 + 3] = v.w;
                }
            }
            __syncthreads();
            {
                int nn = tid >> 2, kg = (tid & 3) * 16;
                uint32_t* dst = (uint32_t*)(outc + (size_t)(tj * 64 + nn) * DD + ti * 64 + kg);
                #pragma unroll
                for (int u = 0; u < 8; ++u) {
                    __half2 h = __floats2half2_rn(ts[(kg + 2 * u) * 65 + nn],
                                                  ts[(kg + 2 * u + 1) * 65 + nn]);
                    dst[u] = h2u(h);
                }
            }
            __syncthreads();
        }
    }
}

// ===========================================================================
// Kernel B (main, fused): per (32-batch-tile, class):
//   1. qW tile [32 x 256] = emb_h @ W1h  — f16 mma, f16 acc, BK=32, 3-stage,
//      FULLY UNROLLED k-loop (compile-time stages + swizzle addresses)
//   2. epilogue: tanh f16x2 + 2nd-stage f16 mma scores (fp32 acc)
//   3. softmax over K, dist via Gram trick, write out
// grid (32, 32), 256 threads (8 warps, warp tile 32x32), 4 CTAs/SM.
// ===========================================================================
__global__ __launch_bounds__(256, 4) void fused_main(
    const float* __restrict__ w2, const float* __restrict__ b2,
    const float* __restrict__ temperature, float* __restrict__ out)
{
    extern __shared__ float sh[];
    uint32_t* shw = (uint32_t*)sh;
    // phase-1: AsW [3][32][16] words 0..1535 ; BsW [3][256][16] words 1536..13823
    // phase-2 layout (aliases phase-1 region)
    uint32_t* sh_pt_h2 = (uint32_t*)sh;        // [16][128] half2 = 2048 words
    float* sh_scorew = sh + 2048;              // [8 warps][32 rows][18] = 4608
    float* sh_w2    = sh + 2048 + 4608;        // 256
    float* sh_G     = sh_w2 + 256;             // [16][17] = 272
    float* sh_inval = sh_G + 272;              // 16      (total 7200 words)

    const int c  = blockIdx.y;
    const int b0 = blockIdx.x * 32;
    const __half* Wh = g_W1h + (size_t)c * DD * DD;   // [n][k] half

    const int tid  = threadIdx.x;
    const int warp = tid >> 5, lane = tid & 31;
    const int wn = warp * 32;            // warp n-slice (all 32 rows)
    const int g  = lane >> 2, tg = lane & 3;

    uint32_t acc[2][4][2];               // f16x2 accumulators [m16][n8][row g/g+8]
    #pragma unroll
    for (int i = 0; i < 2; ++i)
        #pragma unroll
        for (int j = 0; j < 4; ++j) { acc[i][j][0] = 0u; acc[i][j][1] = 0u; }

    // swizzled word index within a stage: row r, chunk ch (0..3), word j (0..3)
    #define SWIZ(r, ch, j) ((r) * 16 + ((((ch) ^ (((r) >> 1) & 3))) << 2) + (j))
    #define ASW(s, r, ch, j) shw[(s) * 512 + SWIZ(r, ch, j)]
    #define BSW(s, r, ch, j) shw[1536 + (s) * 4096 + SWIZ(r, ch, j)]
    #define FM_LOAD(s, kbase)                                                  \
        {                                                                       \
            if (tid < 128) {                                                    \
                int r = tid >> 2, ch = tid & 3;                                 \
                cp16(&ASW(s, r, ch, 0),                                         \
                     g_emb_h + (size_t)(b0 + r) * DD + (kbase) + ch * 8);       \
            }                                                                   \
            _Pragma("unroll")                                                   \
            for (int i_ = 0; i_ < 4; ++i_) {                                    \
                int slot = tid + i_ * 256;                                      \
                int r = slot >> 2, ch = slot & 3;                               \
                cp16(&BSW(s, r, ch, 0),                                         \
                     Wh + (size_t)r * DD + (kbase) + ch * 8);                   \
            }                                                                   \
            CP_COMMIT();                                                        \
        }

    // ---------------- Phase 1: f16 GEMM, FULLY UNROLLED ----------------
    FM_LOAD(0, 0);
    FM_LOAD(1, 32);
    const int NT = DD / 32;   // 8
    #pragma unroll
    for (int kt = 0; kt < NT; ++kt) {
        const int cs = kt % 3;                        // compile-time after unroll
        if (kt < NT - 1) { CP_WAIT(1); } else { CP_WAIT(0); }
        __syncthreads();
        if (kt + 2 < NT) FM_LOAD((kt + 2) % 3, (kt + 2) * 32);

        #pragma unroll
        for (int ks = 0; ks < 2; ++ks) {
            const int c0 = ks * 2;   // chunk pair for this k8-step
            uint32_t afr[2][4], bfr[4][2];
            #pragma unroll
            for (int i = 0; i < 2; ++i) {
                int m0 = i * 16;
                afr[i][0] = ASW(cs, m0 + g,     c0,     tg);
                afr[i][1] = ASW(cs, m0 + g + 8, c0,     tg);
                afr[i][2] = ASW(cs, m0 + g,     c0 + 1, tg);
                afr[i][3] = ASW(cs, m0 + g + 8, c0 + 1, tg);
            }
            #pragma unroll
            for (int j = 0; j < 4; ++j) {
                int n0 = wn + j * 8;
                bfr[j][0] = BSW(cs, n0 + g, c0,     tg);
                bfr[j][1] = BSW(cs, n0 + g, c0 + 1, tg);
            }
            #pragma unroll
            for (int i = 0; i < 2; ++i)
                #pragma unroll
                for (int j = 0; j < 4; ++j)
                    mma_f16_hacc(acc[i][j], afr[i][0], afr[i][1], afr[i][2], afr[i][3],
                                 bfr[j][0], bfr[j][1]);
        }
    }
    __syncthreads();   // all warps done with GEMM smem before repurposing

    // ---------------- Phase 2 tables ----------------
    {
        const float2* ptg2 = (const float2*)(g_proto_term + (size_t)c * KK * DD);
        #pragma unroll
        for (int i = 0; i < 8; ++i) {
            int idx = tid + i * 256;            // 0..2047
            float2 v = ptg2[idx];
            __half2 h = __floats2half2_rn(v.x, v.y);
            sh_pt_h2[idx] = h2u(h);
        }
        if (tid < DD) sh_w2[tid] = w2[c * DD + tid];
        if (tid < KK * KK) sh_G[(tid >> 4) * 17 + (tid & 15)] = g_G[c * 256 + tid];
        if (tid < KK) sh_inval[tid] = g_inval[c * KK + tid];
    }
    __syncthreads();

    // per-thread w2 pairs (B-fragments of 2nd-stage mma)
    uint32_t w2u[4];
    #pragma unroll
    for (int j = 0; j < 4; ++j) {
        float2 w = *(float2*)&sh_w2[wn + j * 8 + 2 * tg];
        w2u[j] = h2u(__floats2half2_rn(w.x, w.y));
    }

    float* my_slab = sh_scorew + warp * 576;   // [32][18]
    const int ptbase = (wn >> 1) + tg;

    // ---------------- Phase 3: tanh + 2nd-stage mma (pt prefetch) ----------
    uint32_t pw_cur[4];
    #pragma unroll
    for (int j = 0; j < 4; ++j) pw_cur[j] = sh_pt_h2[ptbase + j * 4];

    #pragma unroll 1
    for (int k = 0; k < KK; ++k) {
        uint32_t pw_nxt[4];
        if (k + 1 < KK) {
            #pragma unroll
            for (int j = 0; j < 4; ++j)
                pw_nxt[j] = sh_pt_h2[(k + 1) * 128 + ptbase + j * 4];
        }
        __half2 pth[4];
        #pragma unroll
        for (int j = 0; j < 4; ++j) pth[j] = *reinterpret_cast<__half2*>(&pw_cur[j]);

        #pragma unroll
        for (int i = 0; i < 2; ++i) {
            #define ACCH(jj, uu) (*reinterpret_cast<__half2*>(&acc[i][jj][uu]))
            uint32_t t00 = h2u(tanh_h2(__hadd2(ACCH(0, 0), pth[0])));
            uint32_t t01 = h2u(tanh_h2(__hadd2(ACCH(0, 1), pth[0])));
            uint32_t t10 = h2u(tanh_h2(__hadd2(ACCH(1, 0), pth[1])));
            uint32_t t11 = h2u(tanh_h2(__hadd2(ACCH(1, 1), pth[1])));
            uint32_t t20 = h2u(tanh_h2(__hadd2(ACCH(2, 0), pth[2])));
            uint32_t t21 = h2u(tanh_h2(__hadd2(ACCH(2, 1), pth[2])));
            uint32_t t30 = h2u(tanh_h2(__hadd2(ACCH(3, 0), pth[3])));
            uint32_t t31 = h2u(tanh_h2(__hadd2(ACCH(3, 1), pth[3])));
            #undef ACCH

            float cfr[4] = {0.f, 0.f, 0.f, 0.f};
            mma_f16(cfr, t00, t01, t10, t11, w2u[0], w2u[1]);
            mma_f16(cfr, t20, t21, t30, t31, w2u[2], w2u[3]);

            if (tg == 0) {
                my_slab[(i * 16 + g) * 18 + k]     = cfr[0];
                my_slab[(i * 16 + g + 8) * 18 + k] = cfr[2];
            }
        }
        #pragma unroll
        for (int j = 0; j < 4; ++j) pw_cur[j] = pw_nxt[j];
    }
    __syncthreads();

    // ---------------- Phase 4: gather slabs + softmax + Gram distance -------
    if (tid < 32) {
        const int b = b0 + tid;
        const float b2v  = b2[c];
        const float temp = temperature[0];

        float s16[KK];
        #pragma unroll
        for (int k = 0; k < KK; ++k) s16[k] = b2v + sh_inval[k];
        #pragma unroll
        for (int w = 0; w < 8; ++w) {
            const float* p = sh_scorew + w * 576 + tid * 18;
            #pragma unroll
            for (int q = 0; q < 8; ++q) {
                float2 v = *(const float2*)(p + 2 * q);
                s16[2 * q]     += v.x;
                s16[2 * q + 1] += v.y;
            }
        }

        float m = s16[0];
        #pragma unroll
        for (int k = 1; k < KK; ++k) m = fmaxf(m, s16[k]);
        float sum = 0.f;
        #pragma unroll
        for (int k = 0; k < KK; ++k) {
            float e = __expf(s16[k] - m);
            s16[k] = e;
            sum += e;
        }
        float inv = 1.f / sum;
        #pragma unroll
        for (int k = 0; k < KK; ++k) s16[k] *= inv;

        // dist^2 = e2 - 2*attn·dotep + attn^T G attn
        float depv[KK];
        const float4* dep = (const float4*)(g_dotep + (size_t)b * (CC * KK) + c * KK);
        #pragma unroll
        for (int q = 0; q < 4; ++q) {
            float4 v = dep[q];
            depv[4 * q + 0] = v.x; depv[4 * q + 1] = v.y;
            depv[4 * q + 2] = v.z; depv[4 * q + 3] = v.w;
        }
        float dist2 = g_e2[b];
        #pragma unroll
        for (int k = 0; k < KK; ++k)
            dist2 = fmaf(-2.0f * s16[k], depv[k], dist2);
        #pragma unroll
        for (int k = 0; k < KK; ++k) {
            float t = 0.f;
            #pragma unroll
            for (int k2 = 0; k2 < KK; ++k2)
                t = fmaf(sh_G[k * 17 + k2], s16[k2], t);
            dist2 = fmaf(s16[k], t, dist2);
        }
        out[(size_t)b * CC + c] = -sqrtf(fmaxf(dist2, 0.f)) * temp;
    }
    #undef SWIZ
    #undef ASW
    #undef BSW
    #undef FM_LOAD
}

// ---------------------------------------------------------------------------
extern "C" void kernel_launch(void* const* d_in, const int* in_sizes, int n_in,
                              void* d_out, int out_size)
{
    const float* emb    = (const float*)d_in[0];   // [B,D]
    const float* protos = (const float*)d_in[1];   // [C,K,D]
    const float* W1     = (const float*)d_in[2];   // [C,2D,D]
    const float* b1     = (const float*)d_in[3];   // [C,D]
    const float* w2     = (const float*)d_in[4];   // [C,D]
    const float* b2     = (const float*)d_in[5];   // [C]
    const float* temp   = (const float*)d_in[6];   // [1]
    const void*  valid  = (const void*)d_in[7];    // [C,K] bool (storage dtype unknown)
    float* out = (float*)d_out;                    // [B,C]

    // prologue dyn smem: proto_term role needs 16832 words = 67328 B
    const int dynP = 16832 * 4;
    cudaFuncSetAttribute(prologue_kernel, cudaFuncAttributeMaxDynamicSharedMemorySize, dynP);
    // fused_main dyn smem = 13824 words = 55296 B
    const int dyn = 13824 * 4;
    cudaFuncSetAttribute(fused_main, cudaFuncAttributeMaxDynamicSharedMemorySize, dyn);

    prologue_kernel<<<417, 256, dynP>>>(emb, protos, W1, b1, valid);
    fused_main<<<dim3(32, CC), 256, dyn>>>(w2, b2, temp, out);
}